// round 4
// baseline (speedup 1.0000x reference)
#include <cuda_runtime.h>
#include <cuda_fp16.h>
#include <cuda_pipeline.h>

// Problem constants (fixed by the dataset)
#define BATCH   512
#define IN_DIM  256
#define OUT_DIM 256
#define NROWS   68          // G + K = 64 + 4
#define NT      71          // knot count
#define KORD    4

// Tiling
#define BT 64               // batch rows per block
#define CC 16               // input channels per block
#define NB (BATCH / BT)     // 8 batch tiles
#define NC (IN_DIM / CC)    // 16 c-chunks
#define NTHREADS 512
#define OG 32               // o-groups of 8 outputs
#define ROWS_PER_THREAD (BT / (NTHREADS / OG))   // 4

#define W_TILE_H (NROWS * OUT_DIM)               // halfs per tile = 17408 (34 KB)
#define TILE_CHUNKS (W_TILE_H * 2 / 16)          // 16B chunks = 2176
#define SMEM_BYTES ((CC*BT)*16 + (CC*BT)*8 + 2*W_TILE_H*2)   // 94208 B

// fp16 copy of w, [r, c, o] layout, as 16B chunks (8 halfs each)
__device__ uint4 g_wh[NROWS * IN_DIM * OUT_DIM / 8];

__global__ void __launch_bounds__(256, 1)
zero_out_kernel(float* __restrict__ out, int n)
{
    int i = blockIdx.x * blockDim.x + threadIdx.x;
    if (i < n) out[i] = 0.0f;
}

__global__ void __launch_bounds__(512, 2)
convert_w_kernel(const float* __restrict__ w)
{
    int n8 = NROWS * IN_DIM * OUT_DIM / 8;
    for (int i = blockIdx.x * blockDim.x + threadIdx.x; i < n8;
         i += gridDim.x * blockDim.x) {
        const float4* src = (const float4*)w + i * 2;
        float4 a = src[0];
        float4 b = src[1];
        __half2 h0 = __floats2half2_rn(a.x, a.y);
        __half2 h1 = __floats2half2_rn(a.z, a.w);
        __half2 h2 = __floats2half2_rn(b.x, b.y);
        __half2 h3 = __floats2half2_rn(b.z, b.w);
        uint4 o;
        o.x = *(unsigned*)&h0; o.y = *(unsigned*)&h1;
        o.z = *(unsigned*)&h2; o.w = *(unsigned*)&h3;
        g_wh[i] = o;
    }
}

// FMA 8 fp16 weights (one uint4) scaled by s into a[0..7]
__device__ __forceinline__ void h8_fma(float* a, uint4 g, float s)
{
    float2 v;
    v = __half22float2(*(__half2*)&g.x); a[0] = fmaf(s, v.x, a[0]); a[1] = fmaf(s, v.y, a[1]);
    v = __half22float2(*(__half2*)&g.y); a[2] = fmaf(s, v.x, a[2]); a[3] = fmaf(s, v.y, a[3]);
    v = __half22float2(*(__half2*)&g.z); a[4] = fmaf(s, v.x, a[4]); a[5] = fmaf(s, v.y, a[5]);
    v = __half22float2(*(__half2*)&g.w); a[6] = fmaf(s, v.x, a[6]); a[7] = fmaf(s, v.y, a[7]);
}

__global__ void __launch_bounds__(NTHREADS, 1)
kan_main_kernel(const float* __restrict__ x,
                const float* __restrict__ t,
                float* __restrict__ out)
{
    extern __shared__ float smem[];
    float4* s_n4 = (float4*)smem;                    // [CC*BT] spline basis N0..N3
    float2* s_ms = (float2*)(s_n4 + CC*BT);          // [CC*BT] {silu, base_as_int}
    uint4*  s_w  = (uint4*)(s_ms + CC*BT);           // [2][W_TILE_H/8] fp16 w tiles

    const int tid = threadIdx.x;
    const int og  = tid & (OG - 1);    // output group: columns [8*og, 8*og+8)
    const int bq  = tid / OG;          // batch quartet: rows [4*bq, 4*bq+4)
    const int b0  = blockIdx.x * BT;
    const int c0  = blockIdx.y * CC;

    // ---- prefetch first w tile (channel c0) into buffer 0 via cp.async ----
    {
        const int c = c0;
        for (int j = tid; j < TILE_CHUNKS; j += NTHREADS) {
            int r = j >> 5;        // row 0..67
            int q = j & 31;        // 16B chunk within 512B row
            __pipeline_memcpy_async(
                s_w + r * (OUT_DIM / 8) + q,
                g_wh + (size_t)(r * IN_DIM + c) * (OUT_DIM / 8) + q,
                16);
        }
        __pipeline_commit();
    }

    // ---- basis coefficients for this block's (c, b) pairs ----
    for (int e = tid; e < CC * BT; e += NTHREADS) {
        int cl = e >> 6;              // local channel
        int bl = e & 63;              // local batch row
        int c = c0 + cl;
        int b = b0 + bl;
        float xv = __ldg(x + (size_t)b * IN_DIM + c);

        // searchsorted(t, xv, side='right') - 1, clipped to [k-1, NT-k-1]
        int lo = 0, hi = NT;
        while (lo < hi) {
            int mid = (lo + hi) >> 1;
            if (__ldg(t + mid) <= xv) lo = mid + 1; else hi = mid;
        }
        int i = lo - 1;
        i = i < (KORD - 1) ? (KORD - 1) : i;
        i = i > (NT - KORD - 1) ? (NT - KORD - 1) : i;

        float tv0 = __ldg(t + i - 2);
        float tv1 = __ldg(t + i - 1);
        float tv2 = __ldg(t + i);
        float tv3 = __ldg(t + i + 1);
        float tv4 = __ldg(t + i + 2);
        float tv5 = __ldg(t + i + 3);

        float L1 = xv - tv2;
        float L2 = xv - tv1;
        float L3 = xv - tv0;
        float R1 = tv3 - xv;
        float R2 = tv4 - xv;
        float R3 = tv5 - xv;

        // Cox-de Boor, k = 4 (matches reference recurrence in fp32)
        float temp, saved;
        temp = 1.0f / (R1 + L1);
        float n0 = R1 * temp;
        float n1 = L1 * temp;
        temp = n0 / (R1 + L2);
        float m0 = R1 * temp;
        saved = L2 * temp;
        temp = n1 / (R2 + L1);
        float m1 = saved + R2 * temp;
        float m2 = L1 * temp;
        temp = m0 / (R1 + L3);
        float q0 = R1 * temp;
        saved = L3 * temp;
        temp = m1 / (R2 + L2);
        float q1 = saved + R2 * temp;
        saved = L2 * temp;
        temp = m2 / (R3 + L1);
        float q2 = saved + R3 * temp;
        float q3 = L1 * temp;

        float silu = xv / (1.0f + expf(-xv));

        s_n4[e] = make_float4(q0, q1, q2, q3);
        s_ms[e] = make_float2(silu, __int_as_float(i - (KORD - 1)));
    }

    // ---- main loop over channels with double-buffered fp16 w tiles ----
    float acc[ROWS_PER_THREAD][8];
#pragma unroll
    for (int i = 0; i < ROWS_PER_THREAD; i++)
#pragma unroll
        for (int j = 0; j < 8; j++) acc[i][j] = 0.0f;

    for (int ci = 0; ci < CC; ci++) {
        if (ci + 1 < CC) {
            const int c = c0 + ci + 1;
            uint4* dbuf = s_w + ((ci + 1) & 1) * (W_TILE_H / 8);
            for (int j = tid; j < TILE_CHUNKS; j += NTHREADS) {
                int r = j >> 5;
                int q = j & 31;
                __pipeline_memcpy_async(
                    dbuf + r * (OUT_DIM / 8) + q,
                    g_wh + (size_t)(r * IN_DIM + c) * (OUT_DIM / 8) + q,
                    16);
            }
            __pipeline_commit();
            __pipeline_wait_prior(1);   // current tile complete
        } else {
            __pipeline_wait_prior(0);
        }
        __syncthreads();

        const uint4* wb = s_w + (ci & 1) * (W_TILE_H / 8);

        // silu row hoisted, converted once per ci
        float w67f[8];
        {
            uint4 g = wb[67 * (OUT_DIM / 8) + og];
            float2 v;
            v = __half22float2(*(__half2*)&g.x); w67f[0] = v.x; w67f[1] = v.y;
            v = __half22float2(*(__half2*)&g.y); w67f[2] = v.x; w67f[3] = v.y;
            v = __half22float2(*(__half2*)&g.z); w67f[4] = v.x; w67f[5] = v.y;
            v = __half22float2(*(__half2*)&g.w); w67f[6] = v.x; w67f[7] = v.y;
        }

        const float4* n4  = s_n4 + ci * BT + bq * ROWS_PER_THREAD;
        const float2* ms2 = s_ms + ci * BT + bq * ROWS_PER_THREAD;

#pragma unroll
        for (int i = 0; i < ROWS_PER_THREAD; i++) {
            float4 n  = n4[i];                       // broadcast LDS
            float2 ms = ms2[i];                      // broadcast LDS
            int base = __float_as_int(ms.y);
            const uint4* p = wb + base * (OUT_DIM / 8) + og;
            uint4 g0 = p[0 * (OUT_DIM / 8)];
            uint4 g1 = p[1 * (OUT_DIM / 8)];
            uint4 g2 = p[2 * (OUT_DIM / 8)];
            uint4 g3 = p[3 * (OUT_DIM / 8)];
            h8_fma(acc[i], g0, n.x);
            h8_fma(acc[i], g1, n.y);
            h8_fma(acc[i], g2, n.z);
            h8_fma(acc[i], g3, n.w);
#pragma unroll
            for (int j = 0; j < 8; j++)
                acc[i][j] = fmaf(ms.x, w67f[j], acc[i][j]);
        }
        __syncthreads();   // protect buffer reuse by next prefetch
    }

    // ---- combine partials across c-chunks ----
#pragma unroll
    for (int i = 0; i < ROWS_PER_THREAD; i++) {
        float* dst = out + (size_t)(b0 + bq * ROWS_PER_THREAD + i) * OUT_DIM + og * 8;
#pragma unroll
        for (int j = 0; j < 8; j++)
            atomicAdd(dst + j, acc[i][j]);
    }
}

extern "C" void kernel_launch(void* const* d_in, const int* in_sizes, int n_in,
                              void* d_out, int out_size)
{
    const float* x = (const float*)d_in[0];
    const float* w = (const float*)d_in[1];
    const float* t = (const float*)d_in[2];
    float* out = (float*)d_out;

    cudaFuncSetAttribute(kan_main_kernel,
                         cudaFuncAttributeMaxDynamicSharedMemorySize, SMEM_BYTES);

    convert_w_kernel<<<544, 512>>>(w);
    zero_out_kernel<<<(out_size + 255) / 256, 256>>>(out, out_size);

    dim3 grid(NB, NC);
    kan_main_kernel<<<grid, NTHREADS, SMEM_BYTES>>>(x, t, out);
}